// round 8
// baseline (speedup 1.0000x reference)
#include <cuda_runtime.h>
#include <cuda_fp16.h>
#include <cstdint>
#include <cstddef>

#define INNER 31999
#define VOCAB 32000
#define DEPTH 18
#define NROWS 64          // B*T
#define KDIM  512
#define MT    128         // nodes per block tile
#define KC    128         // fp16 K elems per chunk (=256B per row)
#define NCHUNK (KDIM / KC)       // 4
#define A_ST 32768               // 128 rows * 256B
#define B_ST 16384               // 64 rows * 256B
#define STB  (A_ST + B_ST)       // 49152
#define SMEM_TOTAL (2 * STB)     // 98304

// Log-prob table: [2*node + side][row], fp16. side 0 = log sigma, side 1 = log(1-sigma).
__device__ __half g_L[(size_t)2 * VOCAB * NROWS];
// att pre-converted to fp16, row-major [64][512]
__device__ __half g_att16[NROWS * KDIM];

// ---------------- helpers ----------------
__device__ __forceinline__ uint32_t smem_u32(const void* p) {
    return (uint32_t)__cvta_generic_to_shared(p);
}
__device__ __forceinline__ void cp_async16(uint32_t dst, const void* src) {
    asm volatile("cp.async.cg.shared.global [%0], [%1], 16;" :: "r"(dst), "l"(src));
}
__device__ __forceinline__ void cp_commit() { asm volatile("cp.async.commit_group;"); }
template<int N> __device__ __forceinline__ void cp_wait() { asm volatile("cp.async.wait_group %0;" :: "n"(N)); }

__device__ __forceinline__ void ldsm4(uint32_t& r0, uint32_t& r1, uint32_t& r2, uint32_t& r3,
                                      uint32_t addr) {
    asm volatile("ldmatrix.sync.aligned.m8n8.x4.shared.b16 {%0,%1,%2,%3}, [%4];"
                 : "=r"(r0), "=r"(r1), "=r"(r2), "=r"(r3) : "r"(addr));
}
__device__ __forceinline__ void mma_f16(float* c, const uint32_t* a, const uint32_t* b) {
    asm volatile(
        "mma.sync.aligned.m16n8k16.row.col.f32.f16.f16.f32 "
        "{%0,%1,%2,%3}, {%4,%5,%6,%7}, {%8,%9}, {%0,%1,%2,%3};"
        : "+f"(c[0]), "+f"(c[1]), "+f"(c[2]), "+f"(c[3])
        : "r"(a[0]), "r"(a[1]), "r"(a[2]), "r"(a[3]), "r"(b[0]), "r"(b[1]));
}

// ---------------------------------------------------------------------------
// Kernel 0: att fp32 -> fp16 (one-time, 16384 half2)
// ---------------------------------------------------------------------------
__global__ void cvt_att_kernel(const float* __restrict__ att) {
    int i = blockIdx.x * 256 + threadIdx.x;          // 0..16383
    const float2* s = reinterpret_cast<const float2*>(att);
    reinterpret_cast<__half2*>(g_att16)[i] = __float22half2_rn(s[i]);
}

// ---------------------------------------------------------------------------
// Kernel 1: C[128 nodes, 64 rows] per block = W_tile @ att^T.
// fp16 m16n8k16 mma (fp32 acc). A (W) register-staged fp32->fp16; B (att fp16)
// streamed via cp.async. 2-stage smem ring, KC=128 chunks. 256 threads,
// 8 warps (4M x 2N), warp tile 32M x 32N. Softplus epilogue + smem transpose.
// ---------------------------------------------------------------------------
__global__ __launch_bounds__(256, 2) void hs_gemm_kernel(
    const float* __restrict__ att, const float* __restrict__ W)
{
    extern __shared__ char smem[];
    const uint32_t sb = smem_u32(smem);
    (void)att;

    const int tid   = threadIdx.x;
    const int lane  = tid & 31;
    const int warp  = tid >> 5;
    const int wm    = warp & 3;        // warp M index (rows wm*32..+31)
    const int wn    = warp >> 2;       // warp N index (cols wn*32..+31)
    const int nbase = blockIdx.x * MT;
    const int gid   = lane >> 2;
    const int tig   = lane & 3;

    // -------- A register staging: 16 float4 per thread per chunk --------
    float4 ra[16];
    auto ldg_stage = [&](int t) {
#pragma unroll
        for (int i = 0; i < 16; i++) {             // 128 rows x 32 float4 = 4096
            int u = tid + i * 256;
            int row = u >> 5, f4 = u & 31;
            int wr = nbase + row;
            if (wr < INNER)
                ra[i] = *reinterpret_cast<const float4*>(W + (size_t)wr * KDIM + t * KC + f4 * 4);
            else
                ra[i] = make_float4(0.f, 0.f, 0.f, 0.f);
        }
    };
    // A: convert + STS (swizzle: 16B unit j of row r -> j ^ (r&7), low 3 bits)
    auto sts_A = [&](int buf) {
        const uint32_t base = sb + (uint32_t)buf * STB;
#pragma unroll
        for (int i = 0; i < 16; i++) {
            int u = tid + i * 256;
            int row = u >> 5, f4 = u & 31;
            uint32_t unit = (uint32_t)((f4 >> 1) ^ (row & 7));
            uint32_t off  = base + (uint32_t)(row * 256) + unit * 16 + (uint32_t)(f4 & 1) * 8;
            __half2 p0 = __floats2half2_rn(ra[i].x, ra[i].y);
            __half2 p1 = __floats2half2_rn(ra[i].z, ra[i].w);
            asm volatile("st.shared.v2.b32 [%0], {%1, %2};"
                         :: "r"(off), "r"(*(uint32_t*)&p0), "r"(*(uint32_t*)&p1));
        }
    };
    // B: cp.async fp16 att, 4 x 16B per thread per chunk
    auto ldB = [&](int t, int buf) {
        const uint32_t base = sb + (uint32_t)buf * STB + A_ST;
#pragma unroll
        for (int i = 0; i < 4; i++) {
            int u = tid + i * 256;                 // 64 rows x 16 units = 1024
            int row = u >> 4, un = u & 15;
            uint32_t dst = base + (uint32_t)(row * 256) + (uint32_t)((un ^ (row & 7)) << 4);
            cp_async16(dst, g_att16 + (size_t)row * KDIM + t * KC + un * 8);
        }
    };

    // -------- ldmatrix per-lane address precompute --------
    const int li = lane >> 3;   // matrix index 0..3
    const int lr = lane & 7;    // row within matrix
    const uint32_t kh = (uint32_t)(li >> 1);   // k 16B-half select
    uint32_t aBase[2], aX[2];
#pragma unroll
    for (int mt = 0; mt < 2; mt++) {
        int row = wm * 32 + mt * 16 + lr + ((li & 1) << 3);
        aBase[mt] = (uint32_t)(row * 256);
        aX[mt]    = (uint32_t)(row & 7);
    }
    uint32_t bBase[2], bX[2];
#pragma unroll
    for (int q = 0; q < 2; q++) {
        int row = wn * 32 + q * 16 + lr + ((li & 1) << 3);
        bBase[q] = (uint32_t)(row * 256);
        bX[q]    = (uint32_t)(row & 7);
    }

    float acc[2][4][4];
#pragma unroll
    for (int mt = 0; mt < 2; mt++)
#pragma unroll
        for (int f = 0; f < 4; f++)
#pragma unroll
            for (int c = 0; c < 4; c++) acc[mt][f][c] = 0.0f;

    // -------- prologue --------
    ldg_stage(0);
    sts_A(0);
    ldB(0, 0); cp_commit();
    ldg_stage(1);
    cp_wait<0>();
    __syncthreads();

    for (int t = 0; t < NCHUNK; t++) {
        if (t + 1 < NCHUNK) { sts_A((t + 1) & 1); ldB(t + 1, (t + 1) & 1); cp_commit(); }
        if (t + 2 < NCHUNK) ldg_stage(t + 2);

        const uint32_t Ab = sb + (uint32_t)(t & 1) * STB;
        const uint32_t Bb = Ab + A_ST;
#pragma unroll
        for (int ks = 0; ks < 8; ks++) {          // 8 x k16 per chunk
            uint32_t a[2][4];
#pragma unroll
            for (int mt = 0; mt < 2; mt++)
                ldsm4(a[mt][0], a[mt][1], a[mt][2], a[mt][3],
                      Ab + aBase[mt] + ((((uint32_t)(ks * 2) + kh) ^ aX[mt]) << 4));
            uint32_t b[4][2];
#pragma unroll
            for (int q = 0; q < 2; q++) {
                uint32_t r0, r1, r2, r3;
                ldsm4(r0, r1, r2, r3,
                      Bb + bBase[q] + ((((uint32_t)(ks * 2) + kh) ^ bX[q]) << 4));
                b[q * 2][0] = r0;     b[q * 2][1] = r2;
                b[q * 2 + 1][0] = r1; b[q * 2 + 1][1] = r3;
            }
#pragma unroll
            for (int mt = 0; mt < 2; mt++)
#pragma unroll
                for (int f = 0; f < 4; f++)
                    mma_f16(acc[mt][f], a[mt], b[f]);
        }
        if (t + 1 < NCHUNK) cp_wait<0>();
        __syncthreads();
    }

    // -------- epilogue: softplus -> fp16, smem transpose (swizzled), flat copy --------
#pragma unroll
    for (int mt = 0; mt < 2; mt++) {
#pragma unroll
        for (int m8 = 0; m8 < 2; m8++) {
            const int nl = wm * 32 + mt * 16 + m8 * 8 + gid;     // local node 0..127
            const uint32_t swz = (uint32_t)((nl & 7) << 4);
#pragma unroll
            for (int f = 0; f < 4; f++) {
                float lp[2], ln[2];
#pragma unroll
                for (int u = 0; u < 2; u++) {
                    float h = acc[mt][f][m8 * 2 + u];
                    float l = __logf(1.0f + __expf(-fabsf(h)));
                    lp[u] = fmaxf(fminf(h, 0.0f) - l, -20.7232658f);   // log sigma
                    ln[u] = fmaxf(-fmaxf(h, 0.0f) - l, -20.7232658f);  // log(1-sigma)
                }
                const uint32_t col = (uint32_t)(wn * 64 + f * 16 + tig * 4) ^ swz;
                *reinterpret_cast<__half2*>(smem + (2 * nl)     * 128 + col) = __floats2half2_rn(lp[0], lp[1]);
                *reinterpret_cast<__half2*>(smem + (2 * nl + 1) * 128 + col) = __floats2half2_rn(ln[0], ln[1]);
            }
        }
    }
    __syncthreads();

    char* gdst = reinterpret_cast<char*>(&g_L[(size_t)(2 * nbase) * NROWS]);
#pragma unroll
    for (int i = 0; i < 8; i++) {
        int u = tid + i * 256;               // 16B unit, 0..2047
        int s = u >> 3, j = u & 7;
        uint32_t soff = (uint32_t)(s * 128 + ((j ^ ((s >> 1) & 7)) << 4));
        uint4 v = *reinterpret_cast<const uint4*>(smem + soff);
        *reinterpret_cast<uint4*>(gdst + (size_t)u * 16) = v;
    }
}

// ---------------------------------------------------------------------------
// Kernel 2: 8 words per block (4 warps x 2 words), 128 threads, grid 4000.
// Per word: all 18 table loads issued as an independent batch (36 LDGs in
// flight per warp), then 9 HADD2 + fp32 finish. smem transpose for output.
// ---------------------------------------------------------------------------
#define GWPB 8
__global__ __launch_bounds__(128) void hs_gather_kernel(
    const int* __restrict__ pidx, const float* __restrict__ psign,
    float* __restrict__ out)
{
    __shared__ uint16_t sci[GWPB * DEPTH];      // 144 packed child indices
    __shared__ float tr[NROWS * (GWPB + 1)];    // [row][word], pad 9

    const int tid   = threadIdx.x;
    const int lane  = tid & 31;
    const int warp  = tid >> 5;
    const int wbase = blockIdx.x * GWPB;

    // FIX: strided fill — 144 entries > 128 threads; previous guard left
    // sci[128..143] uninitialized (rel_err 7e-2).
    for (int j = tid; j < GWPB * DEPTH; j += 128) {
        int gj = wbase * DEPTH + j;
        sci[j] = (uint16_t)(2 * pidx[gj] + (psign[gj] < 0.0f ? 1 : 0));
    }
    __syncthreads();

    const __half2* Lp = reinterpret_cast<const __half2*>(g_L);
    const int w0 = warp * 2;

    __half2 v[2][DEPTH];
#pragma unroll
    for (int j = 0; j < 2; j++)
#pragma unroll
        for (int d = 0; d < DEPTH; d++) {
            int ci = sci[(w0 + j) * DEPTH + d];
            v[j][d] = __ldg(&Lp[(size_t)ci * 32 + lane]);   // rows 2*lane, 2*lane+1
        }

#pragma unroll
    for (int j = 0; j < 2; j++) {
        float ax = 0.0f, ay = 0.0f;
#pragma unroll
        for (int p = 0; p < 9; p++) {
            __half2 s  = __hadd2(v[j][2 * p], v[j][2 * p + 1]);
            float2 f   = __half22float2(s);
            ax += f.x; ay += f.y;
        }
        tr[(2 * lane)     * (GWPB + 1) + w0 + j] = ax;
        tr[(2 * lane + 1) * (GWPB + 1) + w0 + j] = ay;
    }
    __syncthreads();

    // 64 rows x 8 words = 512 floats = 128 float4 (one per thread)
    int row = tid >> 1;
    int q   = (tid & 1) * 4;
    float4 o = make_float4(tr[row * (GWPB + 1) + q],     tr[row * (GWPB + 1) + q + 1],
                           tr[row * (GWPB + 1) + q + 2], tr[row * (GWPB + 1) + q + 3]);
    *reinterpret_cast<float4*>(out + (size_t)row * VOCAB + wbase + q) = o;
}

extern "C" void kernel_launch(void* const* d_in, const int* in_sizes, int n_in,
                              void* d_out, int out_size)
{
    (void)in_sizes; (void)n_in; (void)out_size;
    const float* att   = (const float*)d_in[0];
    const float* W     = (const float*)d_in[1];
    const int*   pidx  = (const int*)d_in[2];
    const float* psign = (const float*)d_in[3];
    float* out = (float*)d_out;

    cvt_att_kernel<<<64, 256>>>(att);
    cudaFuncSetAttribute(hs_gemm_kernel, cudaFuncAttributeMaxDynamicSharedMemorySize, SMEM_TOTAL);
    hs_gemm_kernel<<<(INNER + MT - 1) / MT, 256, SMEM_TOTAL>>>(att, W);
    hs_gather_kernel<<<VOCAB / GWPB, 128>>>(pidx, psign, out);
}

// round 9
// speedup vs baseline: 1.0620x; 1.0620x over previous
#include <cuda_runtime.h>
#include <cuda_fp16.h>
#include <cstdint>
#include <cstddef>

#define INNER 31999
#define VOCAB 32000
#define DEPTH 18
#define NROWS 64          // B*T
#define KDIM  512
#define MT    128         // nodes per block tile
#define KC    64          // fp16 K elems per A chunk (=128B per row)
#define NCHUNK (KDIM / KC)       // 8
#define B_BYTES 65536            // 64 rows * 1024B (full K, fp16)
#define A_ST    16384            // 128 rows * 128B per stage
#define SMEM_TOTAL (B_BYTES + 2 * A_ST)   // 98304

// Log-prob table: [2*node + side][row], fp16. side 0 = log sigma, side 1 = log(1-sigma).
__device__ __half g_L[(size_t)2 * VOCAB * NROWS];

// ---------------- helpers ----------------
__device__ __forceinline__ uint32_t smem_u32(const void* p) {
    return (uint32_t)__cvta_generic_to_shared(p);
}
__device__ __forceinline__ void ldsm4(uint32_t& r0, uint32_t& r1, uint32_t& r2, uint32_t& r3,
                                      uint32_t addr) {
    asm volatile("ldmatrix.sync.aligned.m8n8.x4.shared.b16 {%0,%1,%2,%3}, [%4];"
                 : "=r"(r0), "=r"(r1), "=r"(r2), "=r"(r3) : "r"(addr));
}
__device__ __forceinline__ void mma_f16(float* c, const uint32_t* a, const uint32_t* b) {
    asm volatile(
        "mma.sync.aligned.m16n8k16.row.col.f32.f16.f16.f32 "
        "{%0,%1,%2,%3}, {%4,%5,%6,%7}, {%8,%9}, {%0,%1,%2,%3};"
        : "+f"(c[0]), "+f"(c[1]), "+f"(c[2]), "+f"(c[3])
        : "r"(a[0]), "r"(a[1]), "r"(a[2]), "r"(a[3]), "r"(b[0]), "r"(b[1]));
}
__device__ __forceinline__ void sts64(uint32_t off, __half2 p0, __half2 p1) {
    asm volatile("st.shared.v2.b32 [%0], {%1, %2};"
                 :: "r"(off), "r"(*(uint32_t*)&p0), "r"(*(uint32_t*)&p1));
}

// ---------------------------------------------------------------------------
// Kernel 1: C[128 nodes, 64 rows] per block = W_tile @ att^T.
// fp16 m16n8k16 mma (fp32 acc). att converted fp32->fp16 ONCE per block into
// a K-resident smem B tile (64KB); only A (W) streams through a 2-stage ring
// (register-staged LDG -> cvt -> STS). 256 threads, 8 warps (4M x 2N),
// warp tile 32M x 32N. Softplus epilogue + smem transpose + vectorized store.
// ---------------------------------------------------------------------------
__global__ __launch_bounds__(256, 2) void hs_gemm_kernel(
    const float* __restrict__ att, const float* __restrict__ W)
{
    extern __shared__ char smem[];
    const uint32_t sb = smem_u32(smem);          // B tile at sb, A stages at sb+B_BYTES

    const int tid   = threadIdx.x;
    const int lane  = tid & 31;
    const int warp  = tid >> 5;
    const int wm    = warp & 3;        // warp M index (rows wm*32..+31)
    const int wn    = warp >> 2;       // warp N index (cols wn*32..+31)
    const int nbase = blockIdx.x * MT;
    const int gid   = lane >> 2;
    const int tig   = lane & 3;

    // -------- B prologue: att [64x512] fp32 -> fp16 smem, swizzled --------
    // 8192 float4 units; unit j (16B) of row r goes to j ^ (r&7) (low 3 bits).
#pragma unroll
    for (int i = 0; i < 32; i++) {
        int u = tid + i * 256;
        int row = u >> 7, f4 = u & 127;
        float4 v = *reinterpret_cast<const float4*>(att + (size_t)row * KDIM + f4 * 4);
        uint32_t unit = (uint32_t)((f4 >> 1) ^ (row & 7));
        uint32_t off  = sb + (uint32_t)(row * 1024) + unit * 16 + (uint32_t)(f4 & 1) * 8;
        sts64(off, __floats2half2_rn(v.x, v.y), __floats2half2_rn(v.z, v.w));
    }

    // -------- A register staging: 8 float4 per thread per chunk --------
    float4 ra[8];
    auto ldg_stage = [&](int t) {
#pragma unroll
        for (int i = 0; i < 8; i++) {              // 128 rows x 16 float4 = 2048
            int u = tid + i * 256;
            int row = u >> 4, f4 = u & 15;
            int wr = nbase + row;
            if (wr < INNER)
                ra[i] = *reinterpret_cast<const float4*>(W + (size_t)wr * KDIM + t * KC + f4 * 4);
            else
                ra[i] = make_float4(0.f, 0.f, 0.f, 0.f);
        }
    };
    auto sts_A = [&](int buf) {
        const uint32_t base = sb + B_BYTES + (uint32_t)buf * A_ST;
#pragma unroll
        for (int i = 0; i < 8; i++) {
            int u = tid + i * 256;
            int row = u >> 4, f4 = u & 15;
            uint32_t unit = (uint32_t)((f4 >> 1) ^ (row & 7));
            uint32_t off  = base + (uint32_t)(row * 128) + unit * 16 + (uint32_t)(f4 & 1) * 8;
            sts64(off, __floats2half2_rn(ra[i].x, ra[i].y), __floats2half2_rn(ra[i].z, ra[i].w));
        }
    };

    // -------- ldmatrix per-lane address precompute --------
    const int li = lane >> 3;   // matrix index 0..3
    const int lr = lane & 7;    // row within matrix
    const uint32_t kh = (uint32_t)(li >> 1);   // k 16B-half select
    uint32_t aBase[2], aX[2];
#pragma unroll
    for (int mt = 0; mt < 2; mt++) {
        int row = wm * 32 + mt * 16 + lr + ((li & 1) << 3);
        aBase[mt] = sb + B_BYTES + (uint32_t)(row * 128);
        aX[mt]    = (uint32_t)(row & 7);
    }
    uint32_t bBase[2], bX[2];
#pragma unroll
    for (int q = 0; q < 2; q++) {
        int row = wn * 32 + q * 16 + lr + ((li & 1) << 3);
        bBase[q] = sb + (uint32_t)(row * 1024);
        bX[q]    = (uint32_t)(row & 7);
    }

    float acc[2][4][4];
#pragma unroll
    for (int mt = 0; mt < 2; mt++)
#pragma unroll
        for (int f = 0; f < 4; f++)
#pragma unroll
            for (int c = 0; c < 4; c++) acc[mt][f][c] = 0.0f;

    // -------- prologue: A stage 0 in smem, stage 1 in regs --------
    ldg_stage(0);
    sts_A(0);
    ldg_stage(1);
    __syncthreads();                               // B tile + A stage 0 visible

    for (int t = 0; t < NCHUNK; t++) {
        if (t + 1 < NCHUNK) sts_A((t + 1) & 1);    // other buffer; guarded by prev sync
        if (t + 2 < NCHUNK) ldg_stage(t + 2);      // in flight across compute

        const uint32_t Ab = (uint32_t)(t & 1) * A_ST;
#pragma unroll
        for (int ks = 0; ks < 4; ks++) {           // 4 x k16 per chunk
            uint32_t a[2][4];
#pragma unroll
            for (int mt = 0; mt < 2; mt++)
                ldsm4(a[mt][0], a[mt][1], a[mt][2], a[mt][3],
                      aBase[mt] + Ab + ((((uint32_t)(ks * 2) + kh) ^ aX[mt]) << 4));
            uint32_t b[4][2];
#pragma unroll
            for (int q = 0; q < 2; q++) {
                uint32_t r0, r1, r2, r3;
                ldsm4(r0, r1, r2, r3,
                      bBase[q] + ((((uint32_t)(t * 8 + ks * 2) + kh) ^ bX[q]) << 4));
                b[q * 2][0] = r0;     b[q * 2][1] = r2;
                b[q * 2 + 1][0] = r1; b[q * 2 + 1][1] = r3;
            }
#pragma unroll
            for (int mt = 0; mt < 2; mt++)
#pragma unroll
                for (int f = 0; f < 4; f++)
                    mma_f16(acc[mt][f], a[mt], b[f]);
        }
        __syncthreads();
    }

    // -------- epilogue: softplus -> fp16, smem transpose (swizzled), flat copy --------
#pragma unroll
    for (int mt = 0; mt < 2; mt++) {
#pragma unroll
        for (int m8 = 0; m8 < 2; m8++) {
            const int nl = wm * 32 + mt * 16 + m8 * 8 + gid;     // local node 0..127
            const uint32_t swz = (uint32_t)((nl & 7) << 4);
#pragma unroll
            for (int f = 0; f < 4; f++) {
                float lp[2], ln[2];
#pragma unroll
                for (int u = 0; u < 2; u++) {
                    float h = acc[mt][f][m8 * 2 + u];
                    float l = __logf(1.0f + __expf(-fabsf(h)));
                    lp[u] = fmaxf(fminf(h, 0.0f) - l, -20.7232658f);   // log sigma
                    ln[u] = fmaxf(-fmaxf(h, 0.0f) - l, -20.7232658f);  // log(1-sigma)
                }
                const uint32_t col = (uint32_t)(wn * 64 + f * 16 + tig * 4) ^ swz;
                *reinterpret_cast<__half2*>(smem + (2 * nl)     * 128 + col) = __floats2half2_rn(lp[0], lp[1]);
                *reinterpret_cast<__half2*>(smem + (2 * nl + 1) * 128 + col) = __floats2half2_rn(ln[0], ln[1]);
            }
        }
    }
    __syncthreads();

    char* gdst = reinterpret_cast<char*>(&g_L[(size_t)(2 * nbase) * NROWS]);
#pragma unroll
    for (int i = 0; i < 8; i++) {
        int u = tid + i * 256;               // 16B unit, 0..2047
        int s = u >> 3, j = u & 7;
        uint32_t soff = (uint32_t)(s * 128 + ((j ^ ((s >> 1) & 7)) << 4));
        uint4 v = *reinterpret_cast<const uint4*>(smem + soff);
        *reinterpret_cast<uint4*>(gdst + (size_t)u * 16) = v;
    }
}

// ---------------------------------------------------------------------------
// Kernel 2: 8 words per block (4 warps x 2 words), 128 threads, grid 4000.
// Per word: all 18 table loads issued as an independent batch (36 LDGs in
// flight per warp), then 9 HADD2 + fp32 finish. smem transpose for output.
// ---------------------------------------------------------------------------
#define GWPB 8
__global__ __launch_bounds__(128) void hs_gather_kernel(
    const int* __restrict__ pidx, const float* __restrict__ psign,
    float* __restrict__ out)
{
    __shared__ uint16_t sci[GWPB * DEPTH];      // 144 packed child indices
    __shared__ float tr[NROWS * (GWPB + 1)];    // [row][word], pad 9

    const int tid   = threadIdx.x;
    const int lane  = tid & 31;
    const int warp  = tid >> 5;
    const int wbase = blockIdx.x * GWPB;

    for (int j = tid; j < GWPB * DEPTH; j += 128) {
        int gj = wbase * DEPTH + j;
        sci[j] = (uint16_t)(2 * pidx[gj] + (psign[gj] < 0.0f ? 1 : 0));
    }
    __syncthreads();

    const __half2* Lp = reinterpret_cast<const __half2*>(g_L);
    const int w0 = warp * 2;

    __half2 v[2][DEPTH];
#pragma unroll
    for (int j = 0; j < 2; j++)
#pragma unroll
        for (int d = 0; d < DEPTH; d++) {
            int ci = sci[(w0 + j) * DEPTH + d];
            v[j][d] = __ldg(&Lp[(size_t)ci * 32 + lane]);   // rows 2*lane, 2*lane+1
        }

#pragma unroll
    for (int j = 0; j < 2; j++) {
        float ax = 0.0f, ay = 0.0f;
#pragma unroll
        for (int p = 0; p < 9; p++) {
            __half2 s  = __hadd2(v[j][2 * p], v[j][2 * p + 1]);
            float2 f   = __half22float2(s);
            ax += f.x; ay += f.y;
        }
        tr[(2 * lane)     * (GWPB + 1) + w0 + j] = ax;
        tr[(2 * lane + 1) * (GWPB + 1) + w0 + j] = ay;
    }
    __syncthreads();

    // 64 rows x 8 words = 512 floats = 128 float4 (one per thread)
    int row = tid >> 1;
    int q   = (tid & 1) * 4;
    float4 o = make_float4(tr[row * (GWPB + 1) + q],     tr[row * (GWPB + 1) + q + 1],
                           tr[row * (GWPB + 1) + q + 2], tr[row * (GWPB + 1) + q + 3]);
    *reinterpret_cast<float4*>(out + (size_t)row * VOCAB + wbase + q) = o;
}

extern "C" void kernel_launch(void* const* d_in, const int* in_sizes, int n_in,
                              void* d_out, int out_size)
{
    (void)in_sizes; (void)n_in; (void)out_size;
    const float* att   = (const float*)d_in[0];
    const float* W     = (const float*)d_in[1];
    const int*   pidx  = (const int*)d_in[2];
    const float* psign = (const float*)d_in[3];
    float* out = (float*)d_out;

    cudaFuncSetAttribute(hs_gemm_kernel, cudaFuncAttributeMaxDynamicSharedMemorySize, SMEM_TOTAL);
    hs_gemm_kernel<<<(INNER + MT - 1) / MT, 256, SMEM_TOTAL>>>(att, W);
    hs_gather_kernel<<<VOCAB / GWPB, 128>>>(pidx, psign, out);
}